// round 11
// baseline (speedup 1.0000x reference)
#include <cuda_runtime.h>
#include <cuda_bf16.h>
#include <cuda_fp16.h>
#include <cstdint>

// ---------------- problem constants ----------------
#define BB   16
#define CC   256
#define HWN  1024
#define NTOK 16384
#define VN   8192
#define NGRP (VN/8)         // 1024 8-code groups per token

// ---------------- GEMM tiling (int8 IMMA mma.sync path) ----------
#define MT 128              // tokens per CTA
#define VT 128              // codes per CTA
#define KCH 128             // K per chunk (int8 -> 128B rows)
#define NCHUNK (CC/KCH)     // 2
#define ASTR 144            // smem row stride bytes (128B data + 16 pad; conflict-free ldmatrix)
#define ABUF (128*ASTR)     // 18432 bytes per A/B buffer

// int8 quantization: x,codebook ~ N(0,1); SCALE=20 -> +-6.35 sigma, clamp-saturated
#define QSCALE 20.0f
#define QINV   (1.0f/(QSCALE*QSCALE))

// smem layout (bytes): [0,512) esq, [512, 512+2*ABUF) A bufs, then B bufs
#define SM_SE 0
#define SM_A  512
#define SM_B  (512 + 2*ABUF)
#define SM_DYN (512 + 4*ABUF)      // 74240
// epilogue group-min table (128 x 16 fp16 = 4KB) aliases buffers at SM_A

// ---------------- device scratch (allocation-free) ----------------
__device__ float   g_xf[NTOK * CC];            // x fp32 [N][C]
__device__ int8_t  g_x8[NTOK * CC];            // x int8
__device__ int8_t  g_cb8[VN * CC];             // codebook int8
__device__ __half  g_gmin[(size_t)NTOK * NGRP];// per-(token,8-code-group) min (32MB)
__device__ float   g_esq[VN];
__device__ int     g_idx[NTOK];

// ---------------- PTX helpers ----------------
static __device__ __forceinline__ uint32_t smem_u32(const void* p) {
    uint32_t a;
    asm("{ .reg .u64 t; cvta.to.shared.u64 t, %1; cvt.u32.u64 %0, t; }" : "=r"(a) : "l"(p));
    return a;
}
static __device__ __forceinline__ void cp16(uint32_t dst, const void* src) {
    asm volatile("cp.async.cg.shared.global [%0], [%1], 16;" :: "r"(dst), "l"(src));
}
#define CP_COMMIT() asm volatile("cp.async.commit_group;" ::: "memory")
#define CP_WAIT(n)  asm volatile("cp.async.wait_group %0;" :: "n"(n) : "memory")

static __device__ __forceinline__ void ldsm4(uint32_t* r, uint32_t addr) {
    asm volatile("ldmatrix.sync.aligned.m8n8.x4.shared.b16 {%0,%1,%2,%3}, [%4];"
        : "=r"(r[0]), "=r"(r[1]), "=r"(r[2]), "=r"(r[3]) : "r"(addr));
}
// int8 IMMA, K=32, s32 accumulate (exact integer dot)
static __device__ __forceinline__ void mma_s8(int* d, const uint32_t* a,
                                              uint32_t b0, uint32_t b1) {
    asm volatile("mma.sync.aligned.m16n8k32.row.col.s32.s8.s8.s32 "
        "{%0,%1,%2,%3}, {%4,%5,%6,%7}, {%8,%9}, {%0,%1,%2,%3};"
        : "+r"(d[0]), "+r"(d[1]), "+r"(d[2]), "+r"(d[3])
        : "r"(a[0]), "r"(a[1]), "r"(a[2]), "r"(a[3]), "r"(b0), "r"(b1));
}
static __device__ __forceinline__ int8_t to_s8(float v) {
    int i = __float2int_rn(v * QSCALE);
    i = max(-127, min(127, i));
    return (int8_t)i;
}

// ---------------------------------------------------------------------------
// K1: transpose x [B,C,HW] -> g_xf (fp32) / g_x8 (int8), [N][C]
// ---------------------------------------------------------------------------
__global__ void vq_transpose(const float* __restrict__ x) {
    __shared__ float t[32][33];
    const int b = blockIdx.z, c0 = blockIdx.y * 32, hw0 = blockIdx.x * 32;
    const int tx = threadIdx.x, ty = threadIdx.y;
#pragma unroll
    for (int i = 0; i < 4; i++) {
        int c = c0 + ty + i * 8;
        t[ty + i * 8][tx] = x[((size_t)(b * CC + c) << 10) + hw0 + tx];
    }
    __syncthreads();
#pragma unroll
    for (int i = 0; i < 4; i++) {
        int hw = hw0 + ty + i * 8;
        float v = t[tx][ty + i * 8];
        size_t o = (size_t)(b * HWN + hw) * CC + c0 + tx;
        g_xf[o] = v;
        g_x8[o] = to_s8(v);
    }
}

// ---------------------------------------------------------------------------
// K2: prep: esq (fp64-acc), codebook int8
// ---------------------------------------------------------------------------
__global__ void vq_prep(const float* __restrict__ cb) {
    const int v = blockIdx.x * 8 + (threadIdx.x >> 5);
    const int lane = threadIdx.x & 31;
    const float* r = cb + (size_t)v * CC;
    float4 a = *(const float4*)(r + lane * 4);
    float4 b = *(const float4*)(r + 128 + lane * 4);
    int8_t* o = g_cb8 + (size_t)v * CC;
    o[lane * 4 + 0] = to_s8(a.x);
    o[lane * 4 + 1] = to_s8(a.y);
    o[lane * 4 + 2] = to_s8(a.z);
    o[lane * 4 + 3] = to_s8(a.w);
    o[128 + lane * 4 + 0] = to_s8(b.x);
    o[128 + lane * 4 + 1] = to_s8(b.y);
    o[128 + lane * 4 + 2] = to_s8(b.z);
    o[128 + lane * 4 + 3] = to_s8(b.w);
    double s = (double)a.x * a.x + (double)a.y * a.y + (double)a.z * a.z + (double)a.w * a.w
             + (double)b.x * b.x + (double)b.y * b.y + (double)b.z * b.z + (double)b.w * b.w;
#pragma unroll
    for (int off = 16; off > 0; off >>= 1)
        s += __shfl_xor_sync(0xffffffffu, s, off);
    if (lane == 0) g_esq[v] = (float)s;
}

// ---------------------------------------------------------------------------
// K3: int8 IMMA GEMM (128x128 tile) — R10-proven mainloop —
//     epilogue: per-8-code-group min straight from registers (no dist dump)
// ---------------------------------------------------------------------------
__global__ void __launch_bounds__(256) vq_gemm() {
    extern __shared__ char smem[];
    const uint32_t sb = smem_u32(smem);
    float* se = (float*)(smem + SM_SE);

    const int tid  = threadIdx.x;
    const int wid  = tid >> 5;
    const int lane = tid & 31;
    const int n0 = blockIdx.x * MT;
    const int v0 = blockIdx.y * VT;

    if (tid < VT) se[tid] = g_esq[v0 + tid];

    const int8_t* asrc = g_x8  + (size_t)n0 * CC;
    const int8_t* bsrc = g_cb8 + (size_t)v0 * CC;

    // ---- async tile loader: chunk kc (128 int8 wide) -> buffer (kc&1) ----
    auto load_chunk = [&](int kc, int buf) {
        const uint32_t sa  = sb + SM_A + buf * ABUF;
        const uint32_t sbb = sb + SM_B + buf * ABUF;
#pragma unroll
        for (int i = 0; i < 4; i++) {
            int s = tid + 256 * i;          // 0..1023
            int row = s >> 3, seg = s & 7;  // 16B segment of 128B row
            cp16(sa  + row * ASTR + seg * 16, asrc + (size_t)row * CC + kc * KCH + seg * 16);
            cp16(sbb + row * ASTR + seg * 16, bsrc + (size_t)row * CC + kc * KCH + seg * 16);
        }
        CP_COMMIT();
    };

    // warp tiling: 4x2 warps, warp tile 32 rows x 64 cols
    const int warp_r = (wid & 3) * 32;
    const int warp_c = (wid >> 2) * 64;

    // per-thread ldmatrix base offsets (bytes, within a buffer)
    const uint32_t aoff = (uint32_t)((warp_r + (lane & 15)) * ASTR + (lane >> 4) * 16);
    const uint32_t boff = (uint32_t)((warp_c + (lane & 7) + ((lane >> 4) << 3)) * ASTR
                                     + ((lane >> 3) & 1) * 16);

    int acc[2][8][4];
#pragma unroll
    for (int mb = 0; mb < 2; mb++)
#pragma unroll
        for (int nb = 0; nb < 8; nb++)
#pragma unroll
            for (int q = 0; q < 4; q++) acc[mb][nb][q] = 0;

    load_chunk(0, 0);

    for (int kc = 0; kc < NCHUNK; kc++) {
        CP_WAIT(0);
        __syncthreads();
        // safe: after the sync, no warp still reads buf (kc+1)&1
        if (kc + 1 < NCHUNK) load_chunk(kc + 1, (kc + 1) & 1);

        const uint32_t abase = sb + SM_A + (kc & 1) * ABUF + aoff;
        const uint32_t bbase = sb + SM_B + (kc & 1) * ABUF + boff;
#pragma unroll
        for (int ks = 0; ks < 4; ks++) {   // 32 int8 (32 bytes) per step
            uint32_t af[2][4];
            ldsm4(af[0], abase + ks * 32);
            ldsm4(af[1], abase + 16 * ASTR + ks * 32);
            uint32_t bfr[4][4];
#pragma unroll
            for (int p = 0; p < 4; p++)
                ldsm4(bfr[p], bbase + p * 16 * ASTR + ks * 32);
#pragma unroll
            for (int mb = 0; mb < 2; mb++)
#pragma unroll
                for (int p = 0; p < 4; p++) {
                    mma_s8(acc[mb][2 * p],     af[mb], bfr[p][0], bfr[p][1]);
                    mma_s8(acc[mb][2 * p + 1], af[mb], bfr[p][2], bfr[p][3]);
                }
        }
    }
    __syncthreads();   // before group-min table (aliases buffers)

    // ---- per-(row, 8-code-group) min straight from registers ----
    // acc[mb][nb][2h+{0,1}] -> row = warp_r + mb*16 + (lane>>2) + h*8,
    //                          cols warp_c + nb*8 + (lane&3)*2 + {0,1}
    // quad shfl (xor 1,2) folds the 4 lanes -> full 8-col group min.
    __half* sg = (__half*)(smem + SM_A);   // [128][16]
    const int wcol = wid >> 2;             // 0 or 1 -> groups 0..7 / 8..15
#pragma unroll
    for (int mb = 0; mb < 2; mb++)
#pragma unroll
        for (int h = 0; h < 2; h++) {
            const int row = warp_r + mb * 16 + (lane >> 2) + h * 8;
#pragma unroll
            for (int nb = 0; nb < 8; nb++) {
                const int c0 = warp_c + nb * 8 + (lane & 3) * 2;
                float d0 = fmaf(-2.0f * QINV, (float)acc[mb][nb][2 * h],     se[c0]);
                float d1 = fmaf(-2.0f * QINV, (float)acc[mb][nb][2 * h + 1], se[c0 + 1]);
                float m = fminf(d0, d1);
                m = fminf(m, __shfl_xor_sync(0xffffffffu, m, 1));
                m = fminf(m, __shfl_xor_sync(0xffffffffu, m, 2));
                if ((lane & 3) == 0) sg[row * 16 + wcol * 8 + nb] = __float2half(m);
            }
        }
    __syncthreads();

    // coalesced write-out: 256 threads x 16B = 4KB
    {
        const int r = tid >> 1, hh = tid & 1;
        uint4 val = *(const uint4*)(sg + r * 16 + hh * 8);
        *(uint4*)(g_gmin + (size_t)(n0 + r) * NGRP + blockIdx.y * 16 + hh * 8) = val;
    }
}

// ---------------------------------------------------------------------------
// K4: scan: group-min prune -> int8 dp4a rescreen (bit-identical to GEMM)
//     -> exact fp32 rescore of true candidates
// ---------------------------------------------------------------------------
#define MARGIN 6.0f
__global__ void __launch_bounds__(256) vq_scan(const float* __restrict__ cb) {
    const int tid = threadIdx.x;
    const int wid = tid >> 5, lane = tid & 31;
    const int n = blockIdx.x * 8 + wid;

    // load this token's 1024 group mins (128 uint4, 4 per lane)
    const uint4* row4 = (const uint4*)(g_gmin + (size_t)n * NGRP);
    uint4 q[4];
#pragma unroll
    for (int i = 0; i < 4; i++) q[i] = row4[i * 32 + lane];

    float gm = 3.4e38f;
#pragma unroll
    for (int i = 0; i < 4; i++) {
        const __half* hp = (const __half*)&q[i];
#pragma unroll
        for (int j = 0; j < 8; j++) gm = fminf(gm, __half2float(hp[j]));
    }
#pragma unroll
    for (int off = 16; off > 0; off >>= 1)
        gm = fminf(gm, __shfl_xor_sync(0xffffffffu, gm, off));
    const float thr = gm + MARGIN;

    // token data: int8 row (for rescreen) + fp32 row (for exact rescore)
    const uint2 xq = ((const uint2*)(g_x8 + (size_t)n * CC))[lane];
    float xr[8];
    {
        const float4* xp = (const float4*)(g_xf + (size_t)n * CC + lane * 8);
        float4 a = xp[0], b = xp[1];
        xr[0] = a.x; xr[1] = a.y; xr[2] = a.z; xr[3] = a.w;
        xr[4] = b.x; xr[5] = b.y; xr[6] = b.z; xr[7] = b.w;
    }

    float bestd = 3.4e38f;
    int   bestv = 0x7fffffff;

#pragma unroll
    for (int i = 0; i < 4; i++) {
        const __half* hp = (const __half*)&q[i];
#pragma unroll
        for (int j = 0; j < 8; j++) {
            unsigned bal = __ballot_sync(0xffffffffu, __half2float(hp[j]) <= thr);
            while (bal) {
                int src = __ffs(bal) - 1;
                bal &= bal - 1;
                const int g = (i * 32 + src) * 8 + j;   // qualifying 8-code group
#pragma unroll
                for (int c = 0; c < 8; c++) {
                    const int vc = g * 8 + c;
                    // int8 rescreen: bit-identical to GEMM accumulator
                    uint2 eq = ((const uint2*)(g_cb8 + (size_t)vc * CC))[lane];
                    int s = __dp4a((int)xq.x, (int)eq.x, __dp4a((int)xq.y, (int)eq.y, 0));
#pragma unroll
                    for (int off = 16; off > 0; off >>= 1)
                        s += __shfl_xor_sync(0xffffffffu, s, off);
                    float dap = fmaf(-2.0f * QINV, (float)s, __ldg(&g_esq[vc]));
                    if (dap <= thr) {
                        // exact fp32 rescore (warp-distributed dot)
                        const float4* ep = (const float4*)(cb + (size_t)vc * CC + lane * 8);
                        float4 ea = ep[0], eb = ep[1];
                        float t = xr[0] * ea.x;
                        t = fmaf(xr[1], ea.y, t); t = fmaf(xr[2], ea.z, t);
                        t = fmaf(xr[3], ea.w, t); t = fmaf(xr[4], eb.x, t);
                        t = fmaf(xr[5], eb.y, t); t = fmaf(xr[6], eb.z, t);
                        t = fmaf(xr[7], eb.w, t);
#pragma unroll
                        for (int off = 16; off > 0; off >>= 1)
                            t += __shfl_xor_sync(0xffffffffu, t, off);
                        float d = fmaf(-2.0f, t, __ldg(&g_esq[vc]));
                        if (d < bestd || (d == bestd && vc < bestv)) { bestd = d; bestv = vc; }
                    }
                }
            }
        }
    }
    if (lane == 0) g_idx[n] = bestv;
}

// ---------------------------------------------------------------------------
// K5: gather + transpose back
// ---------------------------------------------------------------------------
__global__ void vq_gather(const float* __restrict__ cb, float* __restrict__ out) {
    __shared__ float t[32][33];
    const int b = blockIdx.z, c0 = blockIdx.y * 32, hw0 = blockIdx.x * 32;
    const int tx = threadIdx.x, ty = threadIdx.y;
#pragma unroll
    for (int i = 0; i < 4; i++) {
        int row = ty + i * 8;
        int code = g_idx[b * HWN + hw0 + row];
        t[row][tx] = cb[(size_t)code * CC + c0 + tx];
    }
    __syncthreads();
#pragma unroll
    for (int i = 0; i < 4; i++) {
        int c = c0 + ty + i * 8;
        out[((size_t)(b * CC + c) << 10) + hw0 + tx] = t[tx][ty + i * 8];
    }
}

// ---------------------------------------------------------------------------
extern "C" void kernel_launch(void* const* d_in, const int* in_sizes, int n_in,
                              void* d_out, int out_size) {
    const float* x  = (const float*)d_in[0];
    const float* cb = (const float*)d_in[1];
    float* out = (float*)d_out;

    cudaFuncSetAttribute(vq_gemm, cudaFuncAttributeMaxDynamicSharedMemorySize, SM_DYN);

    vq_transpose<<<dim3(HWN / 32, CC / 32, BB), dim3(32, 8)>>>(x);
    vq_prep<<<VN / 8, 256>>>(cb);
    vq_gemm<<<dim3(NTOK / MT, VN / VT), 256, SM_DYN>>>();
    vq_scan<<<NTOK / 8, 256>>>(cb);
    vq_gather<<<dim3(HWN / 32, CC / 32, BB), dim3(32, 8)>>>(cb, out);
}

// round 12
// speedup vs baseline: 1.4797x; 1.4797x over previous
#include <cuda_runtime.h>
#include <cuda_bf16.h>
#include <cuda_fp16.h>
#include <cstdint>

// ---------------- problem constants ----------------
#define BB   16
#define CC   256
#define HWN  1024
#define NTOK 16384
#define VN   8192
#define NGRP (VN/8)         // 1024 8-code groups per token

// ---------------- GEMM tiling (int8 IMMA mma.sync path) ----------
#define MT 128              // tokens per CTA
#define VT 128              // codes per CTA
#define KCH 128             // K per chunk (int8 -> 128B rows)
#define NCHUNK (CC/KCH)     // 2
#define ASTR 144            // smem row stride bytes (128B data + 16 pad; conflict-free ldmatrix)
#define ABUF (128*ASTR)     // 18432 bytes per A/B buffer

// int8 quantization: x,codebook ~ N(0,1); SCALE=20 -> +-6.35 sigma, clamp-saturated
#define QSCALE 20.0f
#define QINV   (1.0f/(QSCALE*QSCALE))

// smem layout (bytes): [0,512) esq, [512, 512+2*ABUF) A bufs, then B bufs
#define SM_SE 0
#define SM_A  512
#define SM_B  (512 + 2*ABUF)
#define SM_DYN (512 + 4*ABUF)      // 74240
// epilogue group-min table (128 x 16 fp16 = 4KB) aliases buffers at SM_A

// ---------------- device scratch (allocation-free) ----------------
__device__ float   g_xf[NTOK * CC];            // x fp32 [N][C]
__device__ int8_t  g_x8[NTOK * CC];            // x int8
__device__ int8_t  g_cb8[VN * CC];             // codebook int8
__device__ __half  g_gmin[(size_t)NTOK * NGRP];// per-(token,8-code-group) min (32MB)
__device__ float   g_esq[VN];
__device__ int     g_idx[NTOK];

// ---------------- PTX helpers ----------------
static __device__ __forceinline__ uint32_t smem_u32(const void* p) {
    uint32_t a;
    asm("{ .reg .u64 t; cvta.to.shared.u64 t, %1; cvt.u32.u64 %0, t; }" : "=r"(a) : "l"(p));
    return a;
}
static __device__ __forceinline__ void cp16(uint32_t dst, const void* src) {
    asm volatile("cp.async.cg.shared.global [%0], [%1], 16;" :: "r"(dst), "l"(src));
}
#define CP_COMMIT() asm volatile("cp.async.commit_group;" ::: "memory")
#define CP_WAIT(n)  asm volatile("cp.async.wait_group %0;" :: "n"(n) : "memory")

static __device__ __forceinline__ void ldsm4(uint32_t* r, uint32_t addr) {
    asm volatile("ldmatrix.sync.aligned.m8n8.x4.shared.b16 {%0,%1,%2,%3}, [%4];"
        : "=r"(r[0]), "=r"(r[1]), "=r"(r[2]), "=r"(r[3]) : "r"(addr));
}
// int8 IMMA, K=32, s32 accumulate (exact integer dot)
static __device__ __forceinline__ void mma_s8(int* d, const uint32_t* a,
                                              uint32_t b0, uint32_t b1) {
    asm volatile("mma.sync.aligned.m16n8k32.row.col.s32.s8.s8.s32 "
        "{%0,%1,%2,%3}, {%4,%5,%6,%7}, {%8,%9}, {%0,%1,%2,%3};"
        : "+r"(d[0]), "+r"(d[1]), "+r"(d[2]), "+r"(d[3])
        : "r"(a[0]), "r"(a[1]), "r"(a[2]), "r"(a[3]), "r"(b0), "r"(b1));
}
static __device__ __forceinline__ int8_t to_s8(float v) {
    int i = __float2int_rn(v * QSCALE);
    i = max(-127, min(127, i));
    return (int8_t)i;
}

// ---------------------------------------------------------------------------
// K1: transpose x [B,C,HW] -> g_xf (fp32) / g_x8 (int8), [N][C]
// ---------------------------------------------------------------------------
__global__ void vq_transpose(const float* __restrict__ x) {
    __shared__ float t[32][33];
    const int b = blockIdx.z, c0 = blockIdx.y * 32, hw0 = blockIdx.x * 32;
    const int tx = threadIdx.x, ty = threadIdx.y;
#pragma unroll
    for (int i = 0; i < 4; i++) {
        int c = c0 + ty + i * 8;
        t[ty + i * 8][tx] = x[((size_t)(b * CC + c) << 10) + hw0 + tx];
    }
    __syncthreads();
#pragma unroll
    for (int i = 0; i < 4; i++) {
        int hw = hw0 + ty + i * 8;
        float v = t[tx][ty + i * 8];
        size_t o = (size_t)(b * HWN + hw) * CC + c0 + tx;
        g_xf[o] = v;
        g_x8[o] = to_s8(v);
    }
}

// ---------------------------------------------------------------------------
// K2: prep: esq (fp64-acc), codebook int8
// ---------------------------------------------------------------------------
__global__ void vq_prep(const float* __restrict__ cb) {
    const int v = blockIdx.x * 8 + (threadIdx.x >> 5);
    const int lane = threadIdx.x & 31;
    const float* r = cb + (size_t)v * CC;
    float4 a = *(const float4*)(r + lane * 4);
    float4 b = *(const float4*)(r + 128 + lane * 4);
    int8_t* o = g_cb8 + (size_t)v * CC;
    o[lane * 4 + 0] = to_s8(a.x);
    o[lane * 4 + 1] = to_s8(a.y);
    o[lane * 4 + 2] = to_s8(a.z);
    o[lane * 4 + 3] = to_s8(a.w);
    o[128 + lane * 4 + 0] = to_s8(b.x);
    o[128 + lane * 4 + 1] = to_s8(b.y);
    o[128 + lane * 4 + 2] = to_s8(b.z);
    o[128 + lane * 4 + 3] = to_s8(b.w);
    double s = (double)a.x * a.x + (double)a.y * a.y + (double)a.z * a.z + (double)a.w * a.w
             + (double)b.x * b.x + (double)b.y * b.y + (double)b.z * b.z + (double)b.w * b.w;
#pragma unroll
    for (int off = 16; off > 0; off >>= 1)
        s += __shfl_xor_sync(0xffffffffu, s, off);
    if (lane == 0) g_esq[v] = (float)s;
}

// ---------------------------------------------------------------------------
// K3: int8 IMMA GEMM (128x128 tile) — R10-proven mainloop —
//     epilogue: per-8-code-group min straight from registers (no dist dump)
// ---------------------------------------------------------------------------
__global__ void __launch_bounds__(256) vq_gemm() {
    extern __shared__ char smem[];
    const uint32_t sb = smem_u32(smem);
    float* se = (float*)(smem + SM_SE);

    const int tid  = threadIdx.x;
    const int wid  = tid >> 5;
    const int lane = tid & 31;
    const int n0 = blockIdx.x * MT;
    const int v0 = blockIdx.y * VT;

    if (tid < VT) se[tid] = g_esq[v0 + tid];

    const int8_t* asrc = g_x8  + (size_t)n0 * CC;
    const int8_t* bsrc = g_cb8 + (size_t)v0 * CC;

    // ---- async tile loader: chunk kc (128 int8 wide) -> buffer (kc&1) ----
    auto load_chunk = [&](int kc, int buf) {
        const uint32_t sa  = sb + SM_A + buf * ABUF;
        const uint32_t sbb = sb + SM_B + buf * ABUF;
#pragma unroll
        for (int i = 0; i < 4; i++) {
            int s = tid + 256 * i;          // 0..1023
            int row = s >> 3, seg = s & 7;  // 16B segment of 128B row
            cp16(sa  + row * ASTR + seg * 16, asrc + (size_t)row * CC + kc * KCH + seg * 16);
            cp16(sbb + row * ASTR + seg * 16, bsrc + (size_t)row * CC + kc * KCH + seg * 16);
        }
        CP_COMMIT();
    };

    // warp tiling: 4x2 warps, warp tile 32 rows x 64 cols
    const int warp_r = (wid & 3) * 32;
    const int warp_c = (wid >> 2) * 64;

    // per-thread ldmatrix base offsets (bytes, within a buffer)
    const uint32_t aoff = (uint32_t)((warp_r + (lane & 15)) * ASTR + (lane >> 4) * 16);
    const uint32_t boff = (uint32_t)((warp_c + (lane & 7) + ((lane >> 4) << 3)) * ASTR
                                     + ((lane >> 3) & 1) * 16);

    int acc[2][8][4];
#pragma unroll
    for (int mb = 0; mb < 2; mb++)
#pragma unroll
        for (int nb = 0; nb < 8; nb++)
#pragma unroll
            for (int q = 0; q < 4; q++) acc[mb][nb][q] = 0;

    load_chunk(0, 0);

    for (int kc = 0; kc < NCHUNK; kc++) {
        CP_WAIT(0);
        __syncthreads();
        // safe: after the sync, no warp still reads buf (kc+1)&1
        if (kc + 1 < NCHUNK) load_chunk(kc + 1, (kc + 1) & 1);

        const uint32_t abase = sb + SM_A + (kc & 1) * ABUF + aoff;
        const uint32_t bbase = sb + SM_B + (kc & 1) * ABUF + boff;
#pragma unroll
        for (int ks = 0; ks < 4; ks++) {   // 32 int8 (32 bytes) per step
            uint32_t af[2][4];
            ldsm4(af[0], abase + ks * 32);
            ldsm4(af[1], abase + 16 * ASTR + ks * 32);
            uint32_t bfr[4][4];
#pragma unroll
            for (int p = 0; p < 4; p++)
                ldsm4(bfr[p], bbase + p * 16 * ASTR + ks * 32);
#pragma unroll
            for (int mb = 0; mb < 2; mb++)
#pragma unroll
                for (int p = 0; p < 4; p++) {
                    mma_s8(acc[mb][2 * p],     af[mb], bfr[p][0], bfr[p][1]);
                    mma_s8(acc[mb][2 * p + 1], af[mb], bfr[p][2], bfr[p][3]);
                }
        }
    }
    __syncthreads();   // before group-min table (aliases buffers)

    // ---- per-(row, 8-code-group) min straight from registers ----
    __half* sg = (__half*)(smem + SM_A);   // [128][16]
    const int wcol = wid >> 2;             // 0 or 1 -> groups 0..7 / 8..15
#pragma unroll
    for (int mb = 0; mb < 2; mb++)
#pragma unroll
        for (int h = 0; h < 2; h++) {
            const int row = warp_r + mb * 16 + (lane >> 2) + h * 8;
#pragma unroll
            for (int nb = 0; nb < 8; nb++) {
                const int c0 = warp_c + nb * 8 + (lane & 3) * 2;
                float d0 = fmaf(-2.0f * QINV, (float)acc[mb][nb][2 * h],     se[c0]);
                float d1 = fmaf(-2.0f * QINV, (float)acc[mb][nb][2 * h + 1], se[c0 + 1]);
                float m = fminf(d0, d1);
                m = fminf(m, __shfl_xor_sync(0xffffffffu, m, 1));
                m = fminf(m, __shfl_xor_sync(0xffffffffu, m, 2));
                if ((lane & 3) == 0) sg[row * 16 + wcol * 8 + nb] = __float2half(m);
            }
        }
    __syncthreads();

    // coalesced write-out: 256 threads x 16B = 4KB
    {
        const int r = tid >> 1, hh = tid & 1;
        uint4 val = *(const uint4*)(sg + r * 16 + hh * 8);
        *(uint4*)(g_gmin + (size_t)(n0 + r) * NGRP + blockIdx.y * 16 + hh * 8) = val;
    }
}

// ---------------------------------------------------------------------------
// K4: scan: group-min prune -> PARALLEL exact fp32 rescore (quad per code,
//     64 dims per lane, one load wave per qualifying group)
// ---------------------------------------------------------------------------
#define MARGIN 6.0f
__global__ void __launch_bounds__(256) vq_scan(const float* __restrict__ cb) {
    __shared__ float sx[8][256];
    const int tid = threadIdx.x;
    const int wid = tid >> 5, lane = tid & 31;
    const int n = blockIdx.x * 8 + wid;

    // stage this token's fp32 x row into smem
    {
        const float4* xp = (const float4*)(g_xf + (size_t)n * CC + lane * 8);
        float4 a = xp[0], b = xp[1];
        *(float4*)&sx[wid][lane * 8]     = a;
        *(float4*)&sx[wid][lane * 8 + 4] = b;
    }

    // load this token's 1024 group mins (128 uint4, 4 per lane)
    const uint4* row4 = (const uint4*)(g_gmin + (size_t)n * NGRP);
    uint4 q[4];
#pragma unroll
    for (int i = 0; i < 4; i++) q[i] = row4[i * 32 + lane];

    float gm = 3.4e38f;
#pragma unroll
    for (int i = 0; i < 4; i++) {
        const __half* hp = (const __half*)&q[i];
#pragma unroll
        for (int j = 0; j < 8; j++) gm = fminf(gm, __half2float(hp[j]));
    }
#pragma unroll
    for (int off = 16; off > 0; off >>= 1)
        gm = fminf(gm, __shfl_xor_sync(0xffffffffu, gm, off));
    const float thr = gm + MARGIN;
    __syncwarp();

    const int qd = lane >> 2;      // quad -> code within group
    const int l4 = lane & 3;       // lane within quad -> 64-dim slice
    const float* xs = &sx[wid][l4 * 64];

    float bestd = 3.4e38f;
    int   bestv = 0x7fffffff;

#pragma unroll
    for (int i = 0; i < 4; i++) {
        const __half* hp = (const __half*)&q[i];
#pragma unroll
        for (int j = 0; j < 8; j++) {
            unsigned bal = __ballot_sync(0xffffffffu, __half2float(hp[j]) <= thr);
            while (bal) {
                int src = __ffs(bal) - 1;
                bal &= bal - 1;
                const int g  = (i * 32 + src) * 8 + j;  // qualifying group
                const int vc = g * 8 + qd;              // this quad's code
                // exact fp32 dot: lane covers dims [l4*64, l4*64+64)
                const float4* ep = (const float4*)(cb + (size_t)vc * CC + l4 * 64);
                float t0 = 0.f, t1 = 0.f, t2 = 0.f, t3 = 0.f;
#pragma unroll
                for (int k = 0; k < 4; k++) {
                    float4 e0 = ep[4 * k], e1 = ep[4 * k + 1],
                           e2 = ep[4 * k + 2], e3 = ep[4 * k + 3];
                    const float* xk = xs + 16 * k;
                    t0 = fmaf(xk[0],  e0.x, t0); t0 = fmaf(xk[1],  e0.y, t0);
                    t0 = fmaf(xk[2],  e0.z, t0); t0 = fmaf(xk[3],  e0.w, t0);
                    t1 = fmaf(xk[4],  e1.x, t1); t1 = fmaf(xk[5],  e1.y, t1);
                    t1 = fmaf(xk[6],  e1.z, t1); t1 = fmaf(xk[7],  e1.w, t1);
                    t2 = fmaf(xk[8],  e2.x, t2); t2 = fmaf(xk[9],  e2.y, t2);
                    t2 = fmaf(xk[10], e2.z, t2); t2 = fmaf(xk[11], e2.w, t2);
                    t3 = fmaf(xk[12], e3.x, t3); t3 = fmaf(xk[13], e3.y, t3);
                    t3 = fmaf(xk[14], e3.z, t3); t3 = fmaf(xk[15], e3.w, t3);
                }
                float t = (t0 + t1) + (t2 + t3);
                t += __shfl_xor_sync(0xffffffffu, t, 1);
                t += __shfl_xor_sync(0xffffffffu, t, 2);
                float d = fmaf(-2.0f, t, __ldg(&g_esq[vc]));
                if (d < bestd || (d == bestd && vc < bestv)) { bestd = d; bestv = vc; }
            }
        }
    }

    // final warp (dist, idx) reduction; ties -> lowest index
#pragma unroll
    for (int off = 16; off > 0; off >>= 1) {
        float od = __shfl_xor_sync(0xffffffffu, bestd, off);
        int   oi = __shfl_xor_sync(0xffffffffu, bestv, off);
        if (od < bestd || (od == bestd && oi < bestv)) { bestd = od; bestv = oi; }
    }
    if (lane == 0) g_idx[n] = bestv;
}

// ---------------------------------------------------------------------------
// K5: gather + transpose back
// ---------------------------------------------------------------------------
__global__ void vq_gather(const float* __restrict__ cb, float* __restrict__ out) {
    __shared__ float t[32][33];
    const int b = blockIdx.z, c0 = blockIdx.y * 32, hw0 = blockIdx.x * 32;
    const int tx = threadIdx.x, ty = threadIdx.y;
#pragma unroll
    for (int i = 0; i < 4; i++) {
        int row = ty + i * 8;
        int code = g_idx[b * HWN + hw0 + row];
        t[row][tx] = cb[(size_t)code * CC + c0 + tx];
    }
    __syncthreads();
#pragma unroll
    for (int i = 0; i < 4; i++) {
        int c = c0 + ty + i * 8;
        out[((size_t)(b * CC + c) << 10) + hw0 + tx] = t[tx][ty + i * 8];
    }
}

// ---------------------------------------------------------------------------
extern "C" void kernel_launch(void* const* d_in, const int* in_sizes, int n_in,
                              void* d_out, int out_size) {
    const float* x  = (const float*)d_in[0];
    const float* cb = (const float*)d_in[1];
    float* out = (float*)d_out;

    cudaFuncSetAttribute(vq_gemm, cudaFuncAttributeMaxDynamicSharedMemorySize, SM_DYN);

    vq_transpose<<<dim3(HWN / 32, CC / 32, BB), dim3(32, 8)>>>(x);
    vq_prep<<<VN / 8, 256>>>(cb);
    vq_gemm<<<dim3(NTOK / MT, VN / VT), 256, SM_DYN>>>();
    vq_scan<<<NTOK / 8, 256>>>(cb);
    vq_gather<<<dim3(HWN / 32, CC / 32, BB), dim3(32, 8)>>>(cb, out);
}

// round 13
// speedup vs baseline: 1.4912x; 1.0078x over previous
#include <cuda_runtime.h>
#include <cuda_bf16.h>
#include <cuda_fp16.h>
#include <cstdint>

// ---------------- problem constants ----------------
#define BB   16
#define CC   256
#define HWN  1024
#define NTOK 16384
#define VN   8192
#define NGRP (VN/8)         // 1024 8-code groups per token

// ---------------- GEMM tiling (int8 IMMA mma.sync path) ----------
#define MT 128              // tokens per CTA
#define VT 128              // codes per CTA
#define KCH 128             // K per chunk (int8 -> 128B rows)
#define NCHUNK (CC/KCH)     // 2
#define ASTR 144            // smem row stride bytes (128B data + 16 pad; conflict-free ldmatrix)
#define ABUF (128*ASTR)     // 18432 bytes per A/B buffer

// int8 quantization: x,codebook ~ N(0,1); SCALE=20 -> +-6.35 sigma, clamp-saturated
#define QSCALE 20.0f
#define QINV   (1.0f/(QSCALE*QSCALE))

// smem layout (bytes): [0,512) esq, [512, 512+2*ABUF) A bufs, then B bufs
#define SM_SE 0
#define SM_A  512
#define SM_B  (512 + 2*ABUF)
#define SM_DYN (512 + 4*ABUF)      // 74240
// epilogue group-min table (128 x 16 fp16 = 4KB) aliases buffers at SM_A

// ---------------- device scratch (allocation-free) ----------------
__device__ float   g_xf[NTOK * CC];            // x fp32 [N][C]
__device__ int8_t  g_x8[NTOK * CC];            // x int8
__device__ int8_t  g_cb8[VN * CC];             // codebook int8
__device__ __half  g_gmin[(size_t)NTOK * NGRP];// per-(token,8-code-group) min (32MB)
__device__ float   g_esq[VN];
__device__ int     g_idx[NTOK];

// ---------------- PTX helpers ----------------
static __device__ __forceinline__ uint32_t smem_u32(const void* p) {
    uint32_t a;
    asm("{ .reg .u64 t; cvta.to.shared.u64 t, %1; cvt.u32.u64 %0, t; }" : "=r"(a) : "l"(p));
    return a;
}
static __device__ __forceinline__ void cp16(uint32_t dst, const void* src) {
    asm volatile("cp.async.cg.shared.global [%0], [%1], 16;" :: "r"(dst), "l"(src));
}
#define CP_COMMIT() asm volatile("cp.async.commit_group;" ::: "memory")
#define CP_WAIT(n)  asm volatile("cp.async.wait_group %0;" :: "n"(n) : "memory")

static __device__ __forceinline__ void ldsm4(uint32_t* r, uint32_t addr) {
    asm volatile("ldmatrix.sync.aligned.m8n8.x4.shared.b16 {%0,%1,%2,%3}, [%4];"
        : "=r"(r[0]), "=r"(r[1]), "=r"(r[2]), "=r"(r[3]) : "r"(addr));
}
// int8 IMMA, K=32, s32 accumulate (exact integer dot)
static __device__ __forceinline__ void mma_s8(int* d, const uint32_t* a,
                                              uint32_t b0, uint32_t b1) {
    asm volatile("mma.sync.aligned.m16n8k32.row.col.s32.s8.s8.s32 "
        "{%0,%1,%2,%3}, {%4,%5,%6,%7}, {%8,%9}, {%0,%1,%2,%3};"
        : "+r"(d[0]), "+r"(d[1]), "+r"(d[2]), "+r"(d[3])
        : "r"(a[0]), "r"(a[1]), "r"(a[2]), "r"(a[3]), "r"(b0), "r"(b1));
}
static __device__ __forceinline__ int8_t to_s8(float v) {
    int i = __float2int_rn(v * QSCALE);
    i = max(-127, min(127, i));
    return (int8_t)i;
}

// ---------------------------------------------------------------------------
// K1: transpose x [B,C,HW] -> g_xf (fp32) / g_x8 (int8), [N][C]
// ---------------------------------------------------------------------------
__global__ void vq_transpose(const float* __restrict__ x) {
    __shared__ float t[32][33];
    const int b = blockIdx.z, c0 = blockIdx.y * 32, hw0 = blockIdx.x * 32;
    const int tx = threadIdx.x, ty = threadIdx.y;
#pragma unroll
    for (int i = 0; i < 4; i++) {
        int c = c0 + ty + i * 8;
        t[ty + i * 8][tx] = x[((size_t)(b * CC + c) << 10) + hw0 + tx];
    }
    __syncthreads();
#pragma unroll
    for (int i = 0; i < 4; i++) {
        int hw = hw0 + ty + i * 8;
        float v = t[tx][ty + i * 8];
        size_t o = (size_t)(b * HWN + hw) * CC + c0 + tx;
        g_xf[o] = v;
        g_x8[o] = to_s8(v);
    }
}

// ---------------------------------------------------------------------------
// K2: prep: esq (fp64-acc), codebook int8
// ---------------------------------------------------------------------------
__global__ void vq_prep(const float* __restrict__ cb) {
    const int v = blockIdx.x * 8 + (threadIdx.x >> 5);
    const int lane = threadIdx.x & 31;
    const float* r = cb + (size_t)v * CC;
    float4 a = *(const float4*)(r + lane * 4);
    float4 b = *(const float4*)(r + 128 + lane * 4);
    int8_t* o = g_cb8 + (size_t)v * CC;
    o[lane * 4 + 0] = to_s8(a.x);
    o[lane * 4 + 1] = to_s8(a.y);
    o[lane * 4 + 2] = to_s8(a.z);
    o[lane * 4 + 3] = to_s8(a.w);
    o[128 + lane * 4 + 0] = to_s8(b.x);
    o[128 + lane * 4 + 1] = to_s8(b.y);
    o[128 + lane * 4 + 2] = to_s8(b.z);
    o[128 + lane * 4 + 3] = to_s8(b.w);
    double s = (double)a.x * a.x + (double)a.y * a.y + (double)a.z * a.z + (double)a.w * a.w
             + (double)b.x * b.x + (double)b.y * b.y + (double)b.z * b.z + (double)b.w * b.w;
#pragma unroll
    for (int off = 16; off > 0; off >>= 1)
        s += __shfl_xor_sync(0xffffffffu, s, off);
    if (lane == 0) g_esq[v] = (float)s;
}

// ---------------------------------------------------------------------------
// K3: int8 IMMA GEMM (128x128 tile) — proven mainloop —
//     epilogue: per-8-code-group min straight from registers (no dist dump)
// ---------------------------------------------------------------------------
__global__ void __launch_bounds__(256) vq_gemm() {
    extern __shared__ char smem[];
    const uint32_t sb = smem_u32(smem);
    float* se = (float*)(smem + SM_SE);

    const int tid  = threadIdx.x;
    const int wid  = tid >> 5;
    const int lane = tid & 31;
    const int n0 = blockIdx.x * MT;
    const int v0 = blockIdx.y * VT;

    if (tid < VT) se[tid] = g_esq[v0 + tid];

    const int8_t* asrc = g_x8  + (size_t)n0 * CC;
    const int8_t* bsrc = g_cb8 + (size_t)v0 * CC;

    // ---- async tile loader: chunk kc (128 int8 wide) -> buffer (kc&1) ----
    auto load_chunk = [&](int kc, int buf) {
        const uint32_t sa  = sb + SM_A + buf * ABUF;
        const uint32_t sbb = sb + SM_B + buf * ABUF;
#pragma unroll
        for (int i = 0; i < 4; i++) {
            int s = tid + 256 * i;          // 0..1023
            int row = s >> 3, seg = s & 7;  // 16B segment of 128B row
            cp16(sa  + row * ASTR + seg * 16, asrc + (size_t)row * CC + kc * KCH + seg * 16);
            cp16(sbb + row * ASTR + seg * 16, bsrc + (size_t)row * CC + kc * KCH + seg * 16);
        }
        CP_COMMIT();
    };

    // warp tiling: 4x2 warps, warp tile 32 rows x 64 cols
    const int warp_r = (wid & 3) * 32;
    const int warp_c = (wid >> 2) * 64;

    // per-thread ldmatrix base offsets (bytes, within a buffer)
    const uint32_t aoff = (uint32_t)((warp_r + (lane & 15)) * ASTR + (lane >> 4) * 16);
    const uint32_t boff = (uint32_t)((warp_c + (lane & 7) + ((lane >> 4) << 3)) * ASTR
                                     + ((lane >> 3) & 1) * 16);

    int acc[2][8][4];
#pragma unroll
    for (int mb = 0; mb < 2; mb++)
#pragma unroll
        for (int nb = 0; nb < 8; nb++)
#pragma unroll
            for (int q = 0; q < 4; q++) acc[mb][nb][q] = 0;

    load_chunk(0, 0);

    for (int kc = 0; kc < NCHUNK; kc++) {
        CP_WAIT(0);
        __syncthreads();
        // safe: after the sync, no warp still reads buf (kc+1)&1
        if (kc + 1 < NCHUNK) load_chunk(kc + 1, (kc + 1) & 1);

        const uint32_t abase = sb + SM_A + (kc & 1) * ABUF + aoff;
        const uint32_t bbase = sb + SM_B + (kc & 1) * ABUF + boff;
#pragma unroll
        for (int ks = 0; ks < 4; ks++) {   // 32 int8 (32 bytes) per step
            uint32_t af[2][4];
            ldsm4(af[0], abase + ks * 32);
            ldsm4(af[1], abase + 16 * ASTR + ks * 32);
            uint32_t bfr[4][4];
#pragma unroll
            for (int p = 0; p < 4; p++)
                ldsm4(bfr[p], bbase + p * 16 * ASTR + ks * 32);
#pragma unroll
            for (int mb = 0; mb < 2; mb++)
#pragma unroll
                for (int p = 0; p < 4; p++) {
                    mma_s8(acc[mb][2 * p],     af[mb], bfr[p][0], bfr[p][1]);
                    mma_s8(acc[mb][2 * p + 1], af[mb], bfr[p][2], bfr[p][3]);
                }
        }
    }
    __syncthreads();   // before group-min table (aliases buffers)

    // ---- per-(row, 8-code-group) min straight from registers ----
    __half* sg = (__half*)(smem + SM_A);   // [128][16]
    const int wcol = wid >> 2;             // 0 or 1 -> groups 0..7 / 8..15
#pragma unroll
    for (int mb = 0; mb < 2; mb++)
#pragma unroll
        for (int h = 0; h < 2; h++) {
            const int row = warp_r + mb * 16 + (lane >> 2) + h * 8;
#pragma unroll
            for (int nb = 0; nb < 8; nb++) {
                const int c0 = warp_c + nb * 8 + (lane & 3) * 2;
                float d0 = fmaf(-2.0f * QINV, (float)acc[mb][nb][2 * h],     se[c0]);
                float d1 = fmaf(-2.0f * QINV, (float)acc[mb][nb][2 * h + 1], se[c0 + 1]);
                float m = fminf(d0, d1);
                m = fminf(m, __shfl_xor_sync(0xffffffffu, m, 1));
                m = fminf(m, __shfl_xor_sync(0xffffffffu, m, 2));
                if ((lane & 3) == 0) sg[row * 16 + wcol * 8 + nb] = __float2half(m);
            }
        }
    __syncthreads();

    // coalesced write-out: 256 threads x 16B = 4KB
    {
        const int r = tid >> 1, hh = tid & 1;
        uint4 val = *(const uint4*)(sg + r * 16 + hh * 8);
        *(uint4*)(g_gmin + (size_t)(n0 + r) * NGRP + blockIdx.y * 16 + hh * 8) = val;
    }
}

// ---------------------------------------------------------------------------
// K4: scan, two-phase: (1) compact qualifying group ids to smem via ballot
//     prefix, (2) runtime loop over list with ONE emitted parallel-rescore
//     body (quad = code, lane = 64-dim slice).
// ---------------------------------------------------------------------------
#define MARGIN 6.0f
#define CANDCAP 128
__global__ void __launch_bounds__(256) vq_scan(const float* __restrict__ cb) {
    __shared__ float sx[8][256];
    __shared__ int   cand[8][CANDCAP];
    const int tid = threadIdx.x;
    const int wid = tid >> 5, lane = tid & 31;
    const int n = blockIdx.x * 8 + wid;

    // stage this token's fp32 x row into smem
    {
        const float4* xp = (const float4*)(g_xf + (size_t)n * CC + lane * 8);
        *(float4*)&sx[wid][lane * 8]     = xp[0];
        *(float4*)&sx[wid][lane * 8 + 4] = xp[1];
    }

    // ---- phase 0: threshold from the 1024 group mins ----
    const uint4* row4 = (const uint4*)(g_gmin + (size_t)n * NGRP);
    uint4 q[4];
#pragma unroll
    for (int i = 0; i < 4; i++) q[i] = row4[i * 32 + lane];

    float gm = 3.4e38f;
#pragma unroll
    for (int i = 0; i < 4; i++) {
        const __half* hp = (const __half*)&q[i];
#pragma unroll
        for (int j = 0; j < 8; j++) gm = fminf(gm, __half2float(hp[j]));
    }
#pragma unroll
    for (int off = 16; off > 0; off >>= 1)
        gm = fminf(gm, __shfl_xor_sync(0xffffffffu, gm, off));
    const float thr = gm + MARGIN;

    // ---- phase 1: compact qualifying group ids (tiny loop body) ----
    const unsigned lmask = (1u << lane) - 1u;
    int cnt = 0;
#pragma unroll
    for (int i = 0; i < 4; i++) {
        const __half* hp = (const __half*)&q[i];
#pragma unroll
        for (int j = 0; j < 8; j++) {
            bool p = __half2float(hp[j]) <= thr;
            unsigned bal = __ballot_sync(0xffffffffu, p);
            if (p) {
                int idx = cnt + __popc(bal & lmask);
                if (idx < CANDCAP) cand[wid][idx] = (i * 32 + lane) * 8 + j;
            }
            cnt += __popc(bal);
        }
    }
    if (cnt > CANDCAP) cnt = CANDCAP;
    __syncwarp();

    // ---- phase 2: parallel exact rescore of candidate groups ----
    const int qd = lane >> 2;      // quad -> code within group
    const int l4 = lane & 3;       // lane within quad -> 64-dim slice
    const float* xs = &sx[wid][l4 * 64];

    float bestd = 3.4e38f;
    int   bestv = 0x7fffffff;

    for (int t = 0; t < cnt; t++) {
        const int g  = cand[wid][t];
        const int vc = g * 8 + qd;
        const float4* ep = (const float4*)(cb + (size_t)vc * CC + l4 * 64);
        float t0 = 0.f, t1 = 0.f, t2 = 0.f, t3 = 0.f;
#pragma unroll
        for (int k = 0; k < 4; k++) {
            float4 e0 = ep[4 * k], e1 = ep[4 * k + 1],
                   e2 = ep[4 * k + 2], e3 = ep[4 * k + 3];
            const float* xk = xs + 16 * k;
            t0 = fmaf(xk[0],  e0.x, t0); t0 = fmaf(xk[1],  e0.y, t0);
            t0 = fmaf(xk[2],  e0.z, t0); t0 = fmaf(xk[3],  e0.w, t0);
            t1 = fmaf(xk[4],  e1.x, t1); t1 = fmaf(xk[5],  e1.y, t1);
            t1 = fmaf(xk[6],  e1.z, t1); t1 = fmaf(xk[7],  e1.w, t1);
            t2 = fmaf(xk[8],  e2.x, t2); t2 = fmaf(xk[9],  e2.y, t2);
            t2 = fmaf(xk[10], e2.z, t2); t2 = fmaf(xk[11], e2.w, t2);
            t3 = fmaf(xk[12], e3.x, t3); t3 = fmaf(xk[13], e3.y, t3);
            t3 = fmaf(xk[14], e3.z, t3); t3 = fmaf(xk[15], e3.w, t3);
        }
        float s = (t0 + t1) + (t2 + t3);
        s += __shfl_xor_sync(0xffffffffu, s, 1);
        s += __shfl_xor_sync(0xffffffffu, s, 2);
        float d = fmaf(-2.0f, s, __ldg(&g_esq[vc]));
        if (d < bestd || (d == bestd && vc < bestv)) { bestd = d; bestv = vc; }
    }

    // final warp (dist, idx) reduction; ties -> lowest index
#pragma unroll
    for (int off = 16; off > 0; off >>= 1) {
        float od = __shfl_xor_sync(0xffffffffu, bestd, off);
        int   oi = __shfl_xor_sync(0xffffffffu, bestv, off);
        if (od < bestd || (od == bestd && oi < bestv)) { bestd = od; bestv = oi; }
    }
    if (lane == 0) g_idx[n] = bestv;
}

// ---------------------------------------------------------------------------
// K5: gather + transpose back
// ---------------------------------------------------------------------------
__global__ void vq_gather(const float* __restrict__ cb, float* __restrict__ out) {
    __shared__ float t[32][33];
    const int b = blockIdx.z, c0 = blockIdx.y * 32, hw0 = blockIdx.x * 32;
    const int tx = threadIdx.x, ty = threadIdx.y;
#pragma unroll
    for (int i = 0; i < 4; i++) {
        int row = ty + i * 8;
        int code = g_idx[b * HWN + hw0 + row];
        t[row][tx] = cb[(size_t)code * CC + c0 + tx];
    }
    __syncthreads();
#pragma unroll
    for (int i = 0; i < 4; i++) {
        int c = c0 + ty + i * 8;
        out[((size_t)(b * CC + c) << 10) + hw0 + tx] = t[tx][ty + i * 8];
    }
}

// ---------------------------------------------------------------------------
extern "C" void kernel_launch(void* const* d_in, const int* in_sizes, int n_in,
                              void* d_out, int out_size) {
    const float* x  = (const float*)d_in[0];
    const float* cb = (const float*)d_in[1];
    float* out = (float*)d_out;

    cudaFuncSetAttribute(vq_gemm, cudaFuncAttributeMaxDynamicSharedMemorySize, SM_DYN);

    vq_transpose<<<dim3(HWN / 32, CC / 32, BB), dim3(32, 8)>>>(x);
    vq_prep<<<VN / 8, 256>>>(cb);
    vq_gemm<<<dim3(NTOK / MT, VN / VT), 256, SM_DYN>>>();
    vq_scan<<<NTOK / 8, 256>>>(cb);
    vq_gather<<<dim3(HWN / 32, CC / 32, BB), dim3(32, 8)>>>(cb, out);
}

// round 14
// speedup vs baseline: 2.1140x; 1.4177x over previous
#include <cuda_runtime.h>
#include <cuda_bf16.h>
#include <cuda_fp16.h>
#include <cstdint>

// ---------------- problem constants ----------------
#define BB   16
#define CC   256
#define HWN  1024
#define NTOK 16384
#define VN   8192
#define NGRP (VN/8)         // 1024 8-code groups per token

// ---------------- GEMM tiling (int8 IMMA mma.sync path) ----------
#define MT 128              // tokens per CTA
#define VT 128              // codes per CTA
#define KCH 128             // K per chunk (int8 -> 128B rows)
#define NCHUNK (CC/KCH)     // 2
#define ASTR 144            // smem row stride bytes (128B data + 16 pad; conflict-free ldmatrix)
#define ABUF (128*ASTR)     // 18432 bytes per A/B buffer

// int8 quantization: x,codebook ~ N(0,1); SCALE=20 -> +-6.35 sigma, clamp-saturated
#define QSCALE 20.0f
#define QINV   (1.0f/(QSCALE*QSCALE))

// smem layout (bytes): [0,512) esq, [512, 512+2*ABUF) A bufs, then B bufs
#define SM_SE 0
#define SM_A  512
#define SM_B  (512 + 2*ABUF)
#define SM_DYN (512 + 4*ABUF)      // 74240
// epilogue group-min table (128 x 16 fp16 = 4KB) aliases buffers at SM_A

// ---------------- device scratch (allocation-free) ----------------
__device__ float   g_xf[NTOK * CC];            // x fp32 [N][C]
__device__ int8_t  g_x8[NTOK * CC];            // x int8
__device__ int8_t  g_cb8[VN * CC];             // codebook int8
__device__ __half  g_gmin[(size_t)NTOK * NGRP];// per-(token,8-code-group) min (32MB)
__device__ float   g_esq[VN];
__device__ int     g_idx[NTOK];

// ---------------- PTX helpers ----------------
static __device__ __forceinline__ uint32_t smem_u32(const void* p) {
    uint32_t a;
    asm("{ .reg .u64 t; cvta.to.shared.u64 t, %1; cvt.u32.u64 %0, t; }" : "=r"(a) : "l"(p));
    return a;
}
static __device__ __forceinline__ void cp16(uint32_t dst, const void* src) {
    asm volatile("cp.async.cg.shared.global [%0], [%1], 16;" :: "r"(dst), "l"(src));
}
#define CP_COMMIT() asm volatile("cp.async.commit_group;" ::: "memory")
#define CP_WAIT(n)  asm volatile("cp.async.wait_group %0;" :: "n"(n) : "memory")

static __device__ __forceinline__ void ldsm4(uint32_t* r, uint32_t addr) {
    asm volatile("ldmatrix.sync.aligned.m8n8.x4.shared.b16 {%0,%1,%2,%3}, [%4];"
        : "=r"(r[0]), "=r"(r[1]), "=r"(r[2]), "=r"(r[3]) : "r"(addr));
}
// int8 IMMA, K=32, s32 accumulate (exact integer dot)
static __device__ __forceinline__ void mma_s8(int* d, const uint32_t* a,
                                              uint32_t b0, uint32_t b1) {
    asm volatile("mma.sync.aligned.m16n8k32.row.col.s32.s8.s8.s32 "
        "{%0,%1,%2,%3}, {%4,%5,%6,%7}, {%8,%9}, {%0,%1,%2,%3};"
        : "+r"(d[0]), "+r"(d[1]), "+r"(d[2]), "+r"(d[3])
        : "r"(a[0]), "r"(a[1]), "r"(a[2]), "r"(a[3]), "r"(b0), "r"(b1));
}
static __device__ __forceinline__ int8_t to_s8(float v) {
    int i = __float2int_rn(v * QSCALE);
    i = max(-127, min(127, i));
    return (int8_t)i;
}

// ---------------------------------------------------------------------------
// K1: transpose x [B,C,HW] -> g_xf (fp32) / g_x8 (int8), [N][C]
// ---------------------------------------------------------------------------
__global__ void vq_transpose(const float* __restrict__ x) {
    __shared__ float t[32][33];
    const int b = blockIdx.z, c0 = blockIdx.y * 32, hw0 = blockIdx.x * 32;
    const int tx = threadIdx.x, ty = threadIdx.y;
#pragma unroll
    for (int i = 0; i < 4; i++) {
        int c = c0 + ty + i * 8;
        t[ty + i * 8][tx] = x[((size_t)(b * CC + c) << 10) + hw0 + tx];
    }
    __syncthreads();
#pragma unroll
    for (int i = 0; i < 4; i++) {
        int hw = hw0 + ty + i * 8;
        float v = t[tx][ty + i * 8];
        size_t o = (size_t)(b * HWN + hw) * CC + c0 + tx;
        g_xf[o] = v;
        g_x8[o] = to_s8(v);
    }
}

// ---------------------------------------------------------------------------
// K2: prep: esq (fp64-acc), codebook int8
// ---------------------------------------------------------------------------
__global__ void vq_prep(const float* __restrict__ cb) {
    const int v = blockIdx.x * 8 + (threadIdx.x >> 5);
    const int lane = threadIdx.x & 31;
    const float* r = cb + (size_t)v * CC;
    float4 a = *(const float4*)(r + lane * 4);
    float4 b = *(const float4*)(r + 128 + lane * 4);
    int8_t* o = g_cb8 + (size_t)v * CC;
    o[lane * 4 + 0] = to_s8(a.x);
    o[lane * 4 + 1] = to_s8(a.y);
    o[lane * 4 + 2] = to_s8(a.z);
    o[lane * 4 + 3] = to_s8(a.w);
    o[128 + lane * 4 + 0] = to_s8(b.x);
    o[128 + lane * 4 + 1] = to_s8(b.y);
    o[128 + lane * 4 + 2] = to_s8(b.z);
    o[128 + lane * 4 + 3] = to_s8(b.w);
    double s = (double)a.x * a.x + (double)a.y * a.y + (double)a.z * a.z + (double)a.w * a.w
             + (double)b.x * b.x + (double)b.y * b.y + (double)b.z * b.z + (double)b.w * b.w;
#pragma unroll
    for (int off = 16; off > 0; off >>= 1)
        s += __shfl_xor_sync(0xffffffffu, s, off);
    if (lane == 0) g_esq[v] = (float)s;
}

// ---------------------------------------------------------------------------
// K3: int8 IMMA GEMM (128x128 tile) — proven mainloop —
//     epilogue: per-8-code-group min straight from registers (no dist dump)
// ---------------------------------------------------------------------------
__global__ void __launch_bounds__(256) vq_gemm() {
    extern __shared__ char smem[];
    const uint32_t sb = smem_u32(smem);
    float* se = (float*)(smem + SM_SE);

    const int tid  = threadIdx.x;
    const int wid  = tid >> 5;
    const int lane = tid & 31;
    const int n0 = blockIdx.x * MT;
    const int v0 = blockIdx.y * VT;

    if (tid < VT) se[tid] = g_esq[v0 + tid];

    const int8_t* asrc = g_x8  + (size_t)n0 * CC;
    const int8_t* bsrc = g_cb8 + (size_t)v0 * CC;

    // ---- async tile loader: chunk kc (128 int8 wide) -> buffer (kc&1) ----
    auto load_chunk = [&](int kc, int buf) {
        const uint32_t sa  = sb + SM_A + buf * ABUF;
        const uint32_t sbb = sb + SM_B + buf * ABUF;
#pragma unroll
        for (int i = 0; i < 4; i++) {
            int s = tid + 256 * i;          // 0..1023
            int row = s >> 3, seg = s & 7;  // 16B segment of 128B row
            cp16(sa  + row * ASTR + seg * 16, asrc + (size_t)row * CC + kc * KCH + seg * 16);
            cp16(sbb + row * ASTR + seg * 16, bsrc + (size_t)row * CC + kc * KCH + seg * 16);
        }
        CP_COMMIT();
    };

    // warp tiling: 4x2 warps, warp tile 32 rows x 64 cols
    const int warp_r = (wid & 3) * 32;
    const int warp_c = (wid >> 2) * 64;

    // per-thread ldmatrix base offsets (bytes, within a buffer)
    const uint32_t aoff = (uint32_t)((warp_r + (lane & 15)) * ASTR + (lane >> 4) * 16);
    const uint32_t boff = (uint32_t)((warp_c + (lane & 7) + ((lane >> 4) << 3)) * ASTR
                                     + ((lane >> 3) & 1) * 16);

    int acc[2][8][4];
#pragma unroll
    for (int mb = 0; mb < 2; mb++)
#pragma unroll
        for (int nb = 0; nb < 8; nb++)
#pragma unroll
            for (int q = 0; q < 4; q++) acc[mb][nb][q] = 0;

    load_chunk(0, 0);

    for (int kc = 0; kc < NCHUNK; kc++) {
        CP_WAIT(0);
        __syncthreads();
        // safe: after the sync, no warp still reads buf (kc+1)&1
        if (kc + 1 < NCHUNK) load_chunk(kc + 1, (kc + 1) & 1);

        const uint32_t abase = sb + SM_A + (kc & 1) * ABUF + aoff;
        const uint32_t bbase = sb + SM_B + (kc & 1) * ABUF + boff;
#pragma unroll
        for (int ks = 0; ks < 4; ks++) {   // 32 int8 (32 bytes) per step
            uint32_t af[2][4];
            ldsm4(af[0], abase + ks * 32);
            ldsm4(af[1], abase + 16 * ASTR + ks * 32);
            uint32_t bfr[4][4];
#pragma unroll
            for (int p = 0; p < 4; p++)
                ldsm4(bfr[p], bbase + p * 16 * ASTR + ks * 32);
#pragma unroll
            for (int mb = 0; mb < 2; mb++)
#pragma unroll
                for (int p = 0; p < 4; p++) {
                    mma_s8(acc[mb][2 * p],     af[mb], bfr[p][0], bfr[p][1]);
                    mma_s8(acc[mb][2 * p + 1], af[mb], bfr[p][2], bfr[p][3]);
                }
        }
    }
    __syncthreads();   // before group-min table (aliases buffers)

    // ---- per-(row, 8-code-group) min straight from registers ----
    __half* sg = (__half*)(smem + SM_A);   // [128][16]
    const int wcol = wid >> 2;             // 0 or 1 -> groups 0..7 / 8..15
#pragma unroll
    for (int mb = 0; mb < 2; mb++)
#pragma unroll
        for (int h = 0; h < 2; h++) {
            const int row = warp_r + mb * 16 + (lane >> 2) + h * 8;
#pragma unroll
            for (int nb = 0; nb < 8; nb++) {
                const int c0 = warp_c + nb * 8 + (lane & 3) * 2;
                float d0 = fmaf(-2.0f * QINV, (float)acc[mb][nb][2 * h],     se[c0]);
                float d1 = fmaf(-2.0f * QINV, (float)acc[mb][nb][2 * h + 1], se[c0 + 1]);
                float m = fminf(d0, d1);
                m = fminf(m, __shfl_xor_sync(0xffffffffu, m, 1));
                m = fminf(m, __shfl_xor_sync(0xffffffffu, m, 2));
                if ((lane & 3) == 0) sg[row * 16 + wcol * 8 + nb] = __float2half(m);
            }
        }
    __syncthreads();

    // coalesced write-out: 256 threads x 16B = 4KB
    {
        const int r = tid >> 1, hh = tid & 1;
        uint4 val = *(const uint4*)(sg + r * 16 + hh * 8);
        *(uint4*)(g_gmin + (size_t)(n0 + r) * NGRP + blockIdx.y * 16 + hh * 8) = val;
    }
}

// ---------------------------------------------------------------------------
// K4: scan: (1) compact qualifying group ids, (2) rescore with FULLY
//     COALESCED per-code loads (lane = dims {lane*4, 128+lane*4}),
//     4 codes in flight per batch.
// ---------------------------------------------------------------------------
#define MARGIN 6.0f
#define CANDCAP 128
__global__ void __launch_bounds__(256) vq_scan(const float* __restrict__ cb) {
    __shared__ int cand[8][CANDCAP];
    const int tid = threadIdx.x;
    const int wid = tid >> 5, lane = tid & 31;
    const int n = blockIdx.x * 8 + wid;

    // x slice for this lane (R10-proven layout: perfectly coalesced)
    const float4 xr0 = *(const float4*)(g_xf + (size_t)n * CC + lane * 4);
    const float4 xr1 = *(const float4*)(g_xf + (size_t)n * CC + 128 + lane * 4);

    // ---- phase 0: threshold from the 1024 group mins ----
    const uint4* row4 = (const uint4*)(g_gmin + (size_t)n * NGRP);
    uint4 q[4];
#pragma unroll
    for (int i = 0; i < 4; i++) q[i] = row4[i * 32 + lane];

    float gm = 3.4e38f;
#pragma unroll
    for (int i = 0; i < 4; i++) {
        const __half* hp = (const __half*)&q[i];
#pragma unroll
        for (int j = 0; j < 8; j++) gm = fminf(gm, __half2float(hp[j]));
    }
#pragma unroll
    for (int off = 16; off > 0; off >>= 1)
        gm = fminf(gm, __shfl_xor_sync(0xffffffffu, gm, off));
    const float thr = gm + MARGIN;

    // ---- phase 1: compact qualifying group ids (tiny loop body) ----
    const unsigned lmask = (1u << lane) - 1u;
    int cnt = 0;
#pragma unroll
    for (int i = 0; i < 4; i++) {
        const __half* hp = (const __half*)&q[i];
#pragma unroll
        for (int j = 0; j < 8; j++) {
            bool p = __half2float(hp[j]) <= thr;
            unsigned bal = __ballot_sync(0xffffffffu, p);
            if (p) {
                int idx = cnt + __popc(bal & lmask);
                if (idx < CANDCAP) cand[wid][idx] = (i * 32 + lane) * 8 + j;
            }
            cnt += __popc(bal);
        }
    }
    if (cnt > CANDCAP) cnt = CANDCAP;
    __syncwarp();

    // ---- phase 2: exact fp32 rescore, coalesced, 4 codes in flight ----
    float bestd = 3.4e38f;
    int   bestv = 0x7fffffff;

    for (int t = 0; t < cnt; t++) {
        const int g = cand[wid][t];
        const float* base = cb + (size_t)g * 8 * CC;
#pragma unroll
        for (int half = 0; half < 2; half++) {
            float ds[4];
#pragma unroll
            for (int c = 0; c < 4; c++) {
                const float* rp = base + (half * 4 + c) * CC;
                const float4 e0 = *(const float4*)(rp + lane * 4);        // coalesced
                const float4 e1 = *(const float4*)(rp + 128 + lane * 4);  // coalesced
                float s = xr0.x * e0.x;
                s = fmaf(xr0.y, e0.y, s); s = fmaf(xr0.z, e0.z, s);
                s = fmaf(xr0.w, e0.w, s); s = fmaf(xr1.x, e1.x, s);
                s = fmaf(xr1.y, e1.y, s); s = fmaf(xr1.z, e1.z, s);
                s = fmaf(xr1.w, e1.w, s);
                ds[c] = s;
            }
#pragma unroll
            for (int off = 16; off > 0; off >>= 1) {
                ds[0] += __shfl_xor_sync(0xffffffffu, ds[0], off);
                ds[1] += __shfl_xor_sync(0xffffffffu, ds[1], off);
                ds[2] += __shfl_xor_sync(0xffffffffu, ds[2], off);
                ds[3] += __shfl_xor_sync(0xffffffffu, ds[3], off);
            }
#pragma unroll
            for (int c = 0; c < 4; c++) {
                const int vc = g * 8 + half * 4 + c;
                float d = fmaf(-2.0f, ds[c], __ldg(&g_esq[vc]));
                if (d < bestd || (d == bestd && vc < bestv)) { bestd = d; bestv = vc; }
            }
        }
    }
    if (lane == 0) g_idx[n] = bestv;
}

// ---------------------------------------------------------------------------
// K5: gather + transpose back
// ---------------------------------------------------------------------------
__global__ void vq_gather(const float* __restrict__ cb, float* __restrict__ out) {
    __shared__ float t[32][33];
    const int b = blockIdx.z, c0 = blockIdx.y * 32, hw0 = blockIdx.x * 32;
    const int tx = threadIdx.x, ty = threadIdx.y;
#pragma unroll
    for (int i = 0; i < 4; i++) {
        int row = ty + i * 8;
        int code = g_idx[b * HWN + hw0 + row];
        t[row][tx] = cb[(size_t)code * CC + c0 + tx];
    }
    __syncthreads();
#pragma unroll
    for (int i = 0; i < 4; i++) {
        int c = c0 + ty + i * 8;
        out[((size_t)(b * CC + c) << 10) + hw0 + tx] = t[tx][ty + i * 8];
    }
}

// ---------------------------------------------------------------------------
extern "C" void kernel_launch(void* const* d_in, const int* in_sizes, int n_in,
                              void* d_out, int out_size) {
    const float* x  = (const float*)d_in[0];
    const float* cb = (const float*)d_in[1];
    float* out = (float*)d_out;

    cudaFuncSetAttribute(vq_gemm, cudaFuncAttributeMaxDynamicSharedMemorySize, SM_DYN);

    vq_transpose<<<dim3(HWN / 32, CC / 32, BB), dim3(32, 8)>>>(x);
    vq_prep<<<VN / 8, 256>>>(cb);
    vq_gemm<<<dim3(NTOK / MT, VN / VT), 256, SM_DYN>>>();
    vq_scan<<<NTOK / 8, 256>>>(cb);
    vq_gather<<<dim3(HWN / 32, CC / 32, BB), dim3(32, 8)>>>(cb, out);
}